// round 12
// baseline (speedup 1.0000x reference)
#include <cuda_runtime.h>
#include <cuda_fp16.h>
#include <stdint.h>

#define D_IN   256
#define D_HID  64
#define D_EMB  32
#define MAX_NODES 100000
#define MAX_NNZ   3200000

typedef unsigned long long ull;

// Scratch (static __device__ — no allocation allowed)
__device__ __half g_Hh [MAX_NODES * D_HID];  // x @ W1            (fp16)
__device__ float  g_S1 [MAX_NODES * D_HID];  // A @ H             (fp32)
__device__ __half g_Z1h[MAX_NODES * D_EMB];  // relu(S1+b1) @ W2  (fp16)
__device__ float  g_S2 [MAX_NODES * D_EMB];  // A @ Z1            (fp32)
__device__ __half g_S2h[MAX_NODES * D_EMB];  // fp16 (S2+b2) for decoder

// CSR scratch
__device__ int g_counts  [MAX_NODES];
__device__ int g_rowstart[MAX_NODES + 1];
__device__ int g_cursor  [MAX_NODES];
__device__ ull g_edge    [MAX_NNZ];          // hi32 = val bits, lo32 = src

// ---------------------------------------------------------------------------
// TF32 helpers
// ---------------------------------------------------------------------------
__device__ __forceinline__ unsigned f2tf32(float f) {
    unsigned r;
    asm("cvt.rna.tf32.f32 %0, %1;" : "=r"(r) : "f"(f));
    return r;
}
__device__ __forceinline__ unsigned bits2tf32(unsigned b) {
    unsigned r;
    asm("cvt.rna.tf32.f32 %0, %1;" : "=r"(r) : "r"(b));
    return r;
}

__device__ __forceinline__ void mma_tf32(
    float& d0, float& d1, float& d2, float& d3,
    unsigned a0, unsigned a1, unsigned a2, unsigned a3,
    unsigned b0, unsigned b1)
{
    asm volatile(
        "mma.sync.aligned.m16n8k8.row.col.f32.tf32.tf32.f32 "
        "{%0,%1,%2,%3}, {%4,%5,%6,%7}, {%8,%9}, {%0,%1,%2,%3};"
        : "+f"(d0), "+f"(d1), "+f"(d2), "+f"(d3)
        : "r"(a0), "r"(a1), "r"(a2), "r"(a3), "r"(b0), "r"(b1));
}

__device__ __forceinline__ void cp_async16(unsigned smem_addr, const void* gptr) {
    asm volatile("cp.async.cg.shared.global [%0], [%1], 16;"
                 :: "r"(smem_addr), "l"(gptr));
}

// ---------------------------------------------------------------------------
// CSR build
// ---------------------------------------------------------------------------
__global__ void zero_counts_kernel(int n) {
    int i = blockIdx.x * blockDim.x + threadIdx.x;
    if (i < n) g_counts[i] = 0;
}

__global__ __launch_bounds__(256) void hist_kernel(
    const int* __restrict__ dst, int nnz)
{
    int t = blockIdx.x * blockDim.x + threadIdx.x;
    int base = t * 4;
    if (base >= nnz) return;
    if (base + 3 < nnz) {
        int4 d4 = __ldg((const int4*)dst + t);
        atomicAdd(&g_counts[d4.x], 1);
        atomicAdd(&g_counts[d4.y], 1);
        atomicAdd(&g_counts[d4.z], 1);
        atomicAdd(&g_counts[d4.w], 1);
    } else {
        for (int j = 0; j < 4 && base + j < nnz; j++)
            atomicAdd(&g_counts[__ldg(dst + base + j)], 1);
    }
}

__global__ __launch_bounds__(1024) void scan_kernel(int n) {
    __shared__ int wsums[32];
    int tid  = threadIdx.x;
    int lane = tid & 31, wid = tid >> 5;
    int C  = (n + 1023) >> 10;
    int lo = tid * C;
    int hi = min(lo + C, n);

    int s = 0;
    for (int i = lo; i < hi; i++) s += g_counts[i];

    int v = s;
    #pragma unroll
    for (int d = 1; d < 32; d <<= 1) {
        int t = __shfl_up_sync(0xffffffffu, v, d);
        if (lane >= d) v += t;
    }
    if (lane == 31) wsums[wid] = v;
    __syncthreads();
    if (wid == 0) {
        int w = wsums[lane];
        #pragma unroll
        for (int d = 1; d < 32; d <<= 1) {
            int t = __shfl_up_sync(0xffffffffu, w, d);
            if (lane >= d) w += t;
        }
        wsums[lane] = w;
    }
    __syncthreads();

    int excl = v - s + (wid > 0 ? wsums[wid - 1] : 0);
    int run  = excl;
    for (int i = lo; i < hi; i++) {
        int c = g_counts[i];
        g_rowstart[i] = run;
        g_cursor[i]   = run;
        run += c;
    }
    if (tid == 0) g_rowstart[n] = wsums[31];
}

__global__ __launch_bounds__(256) void scatter_kernel(
    const int* __restrict__ src, const int* __restrict__ dst,
    const float* __restrict__ val, int nnz)
{
    int t = blockIdx.x * blockDim.x + threadIdx.x;
    int base = t * 4;
    if (base >= nnz) return;
    if (base + 3 < nnz) {
        int4   s4 = __ldg((const int4*)src + t);
        int4   d4 = __ldg((const int4*)dst + t);
        float4 v4 = __ldg((const float4*)val + t);
        int p0 = atomicAdd(&g_cursor[d4.x], 1);
        int p1 = atomicAdd(&g_cursor[d4.y], 1);
        int p2 = atomicAdd(&g_cursor[d4.z], 1);
        int p3 = atomicAdd(&g_cursor[d4.w], 1);
        g_edge[p0] = ((ull)__float_as_uint(v4.x) << 32) | (unsigned)s4.x;
        g_edge[p1] = ((ull)__float_as_uint(v4.y) << 32) | (unsigned)s4.y;
        g_edge[p2] = ((ull)__float_as_uint(v4.z) << 32) | (unsigned)s4.z;
        g_edge[p3] = ((ull)__float_as_uint(v4.w) << 32) | (unsigned)s4.w;
    } else {
        for (int j = 0; j < 4 && base + j < nnz; j++) {
            int e = base + j;
            int pos = atomicAdd(&g_cursor[__ldg(dst + e)], 1);
            g_edge[pos] = ((ull)__float_as_uint(__ldg(val + e)) << 32)
                        | (unsigned)__ldg(src + e);
        }
    }
}

// ---------------------------------------------------------------------------
// GEMM1 (TF32 + cp.async double buffer), fp16 output
// ---------------------------------------------------------------------------
#define W_STRIDE 72
#define X_STRIDE 36
#define W_WORDS  (256 * W_STRIDE)
#define X_WORDS  (128 * X_STRIDE)
#define GEMM1_SMEM ((W_WORDS + 2 * X_WORDS) * 4)

__global__ __launch_bounds__(256) void gemm1_tf32_v4(
    const float* __restrict__ x, const float* __restrict__ W1, int n)
{
    extern __shared__ unsigned smem[];
    unsigned* Wsh = smem;                       // [256][72]
    float*    xsf = (float*)(smem + W_WORDS);   // [2][128][36]

    int tid  = threadIdx.x;
    int warp = tid >> 5;
    int lane = tid & 31;
    int row_base = blockIdx.x * 128;
    int wm   = warp * 16;
    int qrow = lane >> 2;
    int qcol = lane & 3;

    unsigned xs_base;
    asm("{ .reg .u64 t; cvta.to.shared.u64 t, %1; cvt.u32.u64 %0, t; }"
        : "=r"(xs_base) : "l"(xsf));

    #pragma unroll
    for (int l = 0; l < 4; l++) {
        int flat = tid + l * 256;
        int r    = flat >> 3;
        int c4   = flat & 7;
        int grow = row_base + r; if (grow >= n) grow = n - 1;
        cp_async16(xs_base + (unsigned)(r * X_STRIDE + c4 * 4) * 4,
                   x + (size_t)grow * D_IN + c4 * 4);
    }
    asm volatile("cp.async.commit_group;");

    #pragma unroll
    for (int l = 0; l < 16; l++) {
        int flat = tid + l * 256;
        int k  = flat >> 4;
        int cc = (flat & 15) * 4;
        float4 w = __ldg((const float4*)(W1 + (size_t)k * 64 + cc));
        Wsh[k * W_STRIDE + cc + 0] = f2tf32(w.x);
        Wsh[k * W_STRIDE + cc + 1] = f2tf32(w.y);
        Wsh[k * W_STRIDE + cc + 2] = f2tf32(w.z);
        Wsh[k * W_STRIDE + cc + 3] = f2tf32(w.w);
    }

    float c[8][4];
    #pragma unroll
    for (int nt = 0; nt < 8; nt++)
        #pragma unroll
        for (int i = 0; i < 4; i++) c[nt][i] = 0.f;

    #pragma unroll
    for (int kc = 0; kc < 8; kc++) {
        if (kc + 1 < 8) {
            int buf = (kc + 1) & 1;
            #pragma unroll
            for (int l = 0; l < 4; l++) {
                int flat = tid + l * 256;
                int r    = flat >> 3;
                int c4   = flat & 7;
                int grow = row_base + r; if (grow >= n) grow = n - 1;
                cp_async16(xs_base + (unsigned)(buf * X_WORDS + r * X_STRIDE + c4 * 4) * 4,
                           x + (size_t)grow * D_IN + (kc + 1) * 32 + c4 * 4);
            }
            asm volatile("cp.async.commit_group;");
            asm volatile("cp.async.wait_group 1;");
        } else {
            asm volatile("cp.async.wait_group 0;");
        }
        __syncthreads();

        const unsigned* xb = (const unsigned*)(xsf + (kc & 1) * X_WORDS);
        #pragma unroll
        for (int k8 = 0; k8 < 4; k8++) {
            int ar = wm + qrow;
            int ac = k8 * 8 + qcol;
            unsigned a0 = bits2tf32(xb[(ar    ) * X_STRIDE + ac    ]);
            unsigned a1 = bits2tf32(xb[(ar + 8) * X_STRIDE + ac    ]);
            unsigned a2 = bits2tf32(xb[(ar    ) * X_STRIDE + ac + 4]);
            unsigned a3 = bits2tf32(xb[(ar + 8) * X_STRIDE + ac + 4]);
            int kg = kc * 32 + k8 * 8 + qcol;
            #pragma unroll
            for (int nt = 0; nt < 8; nt++) {
                unsigned b0 = Wsh[(kg    ) * W_STRIDE + nt * 8 + qrow];
                unsigned b1 = Wsh[(kg + 4) * W_STRIDE + nt * 8 + qrow];
                mma_tf32(c[nt][0], c[nt][1], c[nt][2], c[nt][3],
                         a0, a1, a2, a3, b0, b1);
            }
        }
        __syncthreads();
    }

    int r0 = row_base + wm + qrow;
    int cb = qcol * 2;
    #pragma unroll
    for (int nt = 0; nt < 8; nt++) {
        if (r0 < n)
            *(__half2*)(g_Hh + (size_t)r0 * D_HID + nt*8 + cb) =
                __floats2half2_rn(c[nt][0], c[nt][1]);
        if (r0 + 8 < n)
            *(__half2*)(g_Hh + (size_t)(r0 + 8) * D_HID + nt*8 + cb) =
                __floats2half2_rn(c[nt][2], c[nt][3]);
    }
}

// ---------------------------------------------------------------------------
// SpMM d=64 (CSR): warp per dst row. Lanes load 32 packed edges coalesced;
// 2 groups x 16 lanes each gather/accumulate; single row write, no atomics.
// Padded tail edges have val=0, src=0 (row-0 gathers are L1 hits, harmless).
// ---------------------------------------------------------------------------
__global__ __launch_bounds__(256) void spmm64_csr_kernel(int n)
{
    int warp = (blockIdx.x * blockDim.x + threadIdx.x) >> 5;
    int lane = threadIdx.x & 31;
    if (warp >= n) return;

    int start = g_rowstart[warp];
    int end   = g_rowstart[warp + 1];
    int g = lane >> 4;           // group 0/1
    int c = lane & 15;           // channel quad

    float4 acc = make_float4(0.f, 0.f, 0.f, 0.f);

    for (int b = start; b < end; b += 32) {
        int i = b + lane;
        ull p = (i < end) ? __ldg(g_edge + i) : 0ull;
        #pragma unroll
        for (int j = 0; j < 16; j++) {
            int sl = j * 2 + g;            // interleaved edge assignment
            ull pj = __shfl_sync(0xFFFFFFFFu, p, sl);
            int   sj = (int)(unsigned)(pj & 0xffffffffu);
            float vj = __uint_as_float((unsigned)(pj >> 32));
            uint2 raw = __ldg((const uint2*)(g_Hh + (size_t)sj * D_HID) + c);
            float2 f0 = __half22float2(*(__half2*)&raw.x);
            float2 f1 = __half22float2(*(__half2*)&raw.y);
            acc.x += vj * f0.x;
            acc.y += vj * f0.y;
            acc.z += vj * f1.x;
            acc.w += vj * f1.y;
        }
    }

    // combine the two groups (lane c and c+16 hold the same channels)
    acc.x += __shfl_xor_sync(0xFFFFFFFFu, acc.x, 16);
    acc.y += __shfl_xor_sync(0xFFFFFFFFu, acc.y, 16);
    acc.z += __shfl_xor_sync(0xFFFFFFFFu, acc.z, 16);
    acc.w += __shfl_xor_sync(0xFFFFFFFFu, acc.w, 16);
    if (g == 0)
        *(float4*)(g_S1 + (size_t)warp * D_HID + c * 4) = acc;
}

// ---------------------------------------------------------------------------
// GEMM2: Z1 = relu(S1 + b1) @ W2, fp16 output
// ---------------------------------------------------------------------------
__global__ __launch_bounds__(256) void gemm2_kernel(
    const float* __restrict__ b1, const float* __restrict__ W2, int n)
{
    __shared__ float zs[64][65];
    __shared__ float ws[64][32];

    int tid = threadIdx.x;
    int row_base = blockIdx.x * 64;

    #pragma unroll
    for (int l = 0; l < 4; l++) {
        int flat = tid + l * 256;
        int r  = flat >> 4;
        int c4 = flat & 15;
        float4 v = make_float4(0.f,0.f,0.f,0.f);
        if (row_base + r < n)
            v = *(const float4*)(g_S1 + (size_t)row_base * D_HID + (size_t)flat * 4);
        float4 bb = __ldg((const float4*)b1 + c4);
        v.x = fmaxf(v.x + bb.x, 0.f);
        v.y = fmaxf(v.y + bb.y, 0.f);
        v.z = fmaxf(v.z + bb.z, 0.f);
        v.w = fmaxf(v.w + bb.w, 0.f);
        zs[r][c4*4+0] = v.x; zs[r][c4*4+1] = v.y;
        zs[r][c4*4+2] = v.z; zs[r][c4*4+3] = v.w;
    }
    #pragma unroll
    for (int l = 0; l < 2; l++) {
        int flat = tid + l * 256;
        ((float4*)&ws[0][0])[flat] = __ldg((const float4*)W2 + flat);
    }
    __syncthreads();

    int ty = tid >> 3;
    int tx = tid & 7;
    int col = tx * 4;

    float a00=0,a01=0,a02=0,a03=0;
    float a10=0,a11=0,a12=0,a13=0;

    #pragma unroll 16
    for (int kk = 0; kk < 64; kk++) {
        float z0 = zs[ty*2+0][kk];
        float z1 = zs[ty*2+1][kk];
        float4 b = *(float4*)&ws[kk][col];
        a00 += z0*b.x; a01 += z0*b.y; a02 += z0*b.z; a03 += z0*b.w;
        a10 += z1*b.x; a11 += z1*b.y; a12 += z1*b.z; a13 += z1*b.w;
    }

    int r0 = row_base + ty*2;
    if (r0 + 0 < n) {
        *(__half2*)(g_Z1h + (size_t)(r0+0)*D_EMB + col)     = __floats2half2_rn(a00, a01);
        *(__half2*)(g_Z1h + (size_t)(r0+0)*D_EMB + col + 2) = __floats2half2_rn(a02, a03);
    }
    if (r0 + 1 < n) {
        *(__half2*)(g_Z1h + (size_t)(r0+1)*D_EMB + col)     = __floats2half2_rn(a10, a11);
        *(__half2*)(g_Z1h + (size_t)(r0+1)*D_EMB + col + 2) = __floats2half2_rn(a12, a13);
    }
}

// ---------------------------------------------------------------------------
// SpMM d=32 (CSR): warp per dst row, 4 groups x 8 lanes.
// ---------------------------------------------------------------------------
__global__ __launch_bounds__(256) void spmm32_csr_kernel(int n)
{
    int warp = (blockIdx.x * blockDim.x + threadIdx.x) >> 5;
    int lane = threadIdx.x & 31;
    if (warp >= n) return;

    int start = g_rowstart[warp];
    int end   = g_rowstart[warp + 1];
    int g = lane >> 3;           // group 0..3
    int c = lane & 7;

    float4 acc = make_float4(0.f, 0.f, 0.f, 0.f);

    for (int b = start; b < end; b += 32) {
        int i = b + lane;
        ull p = (i < end) ? __ldg(g_edge + i) : 0ull;
        #pragma unroll
        for (int j = 0; j < 8; j++) {
            int sl = j * 4 + g;
            ull pj = __shfl_sync(0xFFFFFFFFu, p, sl);
            int   sj = (int)(unsigned)(pj & 0xffffffffu);
            float vj = __uint_as_float((unsigned)(pj >> 32));
            uint2 raw = __ldg((const uint2*)(g_Z1h + (size_t)sj * D_EMB) + c);
            float2 f0 = __half22float2(*(__half2*)&raw.x);
            float2 f1 = __half22float2(*(__half2*)&raw.y);
            acc.x += vj * f0.x;
            acc.y += vj * f0.y;
            acc.z += vj * f1.x;
            acc.w += vj * f1.y;
        }
    }

    // combine the four groups (lanes c, c+8, c+16, c+24 hold same channels)
    #pragma unroll
    for (int m = 8; m < 32; m <<= 1) {
        acc.x += __shfl_xor_sync(0xFFFFFFFFu, acc.x, m);
        acc.y += __shfl_xor_sync(0xFFFFFFFFu, acc.y, m);
        acc.z += __shfl_xor_sync(0xFFFFFFFFu, acc.z, m);
        acc.w += __shfl_xor_sync(0xFFFFFFFFu, acc.w, m);
    }
    if (g == 0)
        *(float4*)(g_S2 + (size_t)warp * D_EMB + c * 4) = acc;
}

// ---------------------------------------------------------------------------
// S2 fp32 -> fp16 with fused +b2.
// ---------------------------------------------------------------------------
__global__ __launch_bounds__(256) void s2half_kernel(
    const float* __restrict__ b2, int n4)
{
    int i = blockIdx.x * blockDim.x + threadIdx.x;
    if (i >= n4) return;
    float4 bb = __ldg((const float4*)b2 + (i & 7));
    float4 v = ((const float4*)g_S2)[i];
    ((__half2*)g_S2h)[i*2    ] = __floats2half2_rn(v.x + bb.x, v.y + bb.y);
    ((__half2*)g_S2h)[i*2 + 1] = __floats2half2_rn(v.z + bb.z, v.w + bb.w);
}

// ---------------------------------------------------------------------------
// Decoder: warp owns 32 edges; coalesced index loads + shfl distribution.
// ---------------------------------------------------------------------------
__global__ __launch_bounds__(256) void decoder_kernel(
    const int* __restrict__ edge_index, float* __restrict__ out, int ne)
{
    int lane = threadIdx.x & 31;
    long long wid = (long long)((blockIdx.x * blockDim.x + threadIdx.x) >> 5);
    long long wbase = wid * 32;
    if (wbase >= ne) return;

    long long e = wbase + lane;
    bool ok = (e < ne);
    long long ec = ok ? e : (ne - 1);
    int s = __ldg(edge_index + ec);
    int d = __ldg(edge_index + ne + ec);

    int g = lane >> 3;
    int c = lane & 7;

    float p[8];
    #pragma unroll
    for (int j = 0; j < 8; j++) {
        int sl = g * 8 + j;
        int sj = __shfl_sync(0xFFFFFFFFu, s, sl);
        int dj = __shfl_sync(0xFFFFFFFFu, d, sl);
        uint2 ra = __ldg((const uint2*)(g_S2h + (size_t)sj * D_EMB) + c);
        uint2 rb = __ldg((const uint2*)(g_S2h + (size_t)dj * D_EMB) + c);
        float2 al = __half22float2(*(__half2*)&ra.x);
        float2 ah = __half22float2(*(__half2*)&ra.y);
        float2 bl = __half22float2(*(__half2*)&rb.x);
        float2 bh = __half22float2(*(__half2*)&rb.y);
        p[j] = al.x*bl.x + al.y*bl.y + ah.x*bh.x + ah.y*bh.y;
    }

    #pragma unroll
    for (int m = 1; m < 8; m <<= 1) {
        #pragma unroll
        for (int j = 0; j < 8; j++)
            p[j] += __shfl_xor_sync(0xFFFFFFFFu, p[j], m);
    }

    long long eo = wbase + g * 8 + c;
    if (eo < ne) out[eo] = p[c];
}

// ---------------------------------------------------------------------------
extern "C" void kernel_launch(void* const* d_in, const int* in_sizes, int n_in,
                              void* d_out, int out_size)
{
    const float* x         = (const float*)d_in[0];
    const int*   adj_src   = (const int*)  d_in[1];
    const int*   adj_dst   = (const int*)  d_in[2];
    const float* adj_val   = (const float*)d_in[3];
    const int*   edge_idx  = (const int*)  d_in[4];
    const float* W1        = (const float*)d_in[5];
    const float* b1        = (const float*)d_in[6];
    const float* W2        = (const float*)d_in[7];
    const float* b2        = (const float*)d_in[8];
    float*       out       = (float*)d_out;

    int n   = in_sizes[0] / D_IN;
    int nnz = in_sizes[3];
    int ne  = in_sizes[4] / 2;
    (void)n_in; (void)out_size;

    // --- CSR build (MLP=4 batched) ---
    zero_counts_kernel<<<(n + 255) / 256, 256>>>(n);
    {
        int tgroups = (nnz + 3) / 4;
        hist_kernel<<<(tgroups + 255) / 256, 256>>>(adj_dst, nnz);
    }
    scan_kernel<<<1, 1024>>>(n);
    {
        int tgroups = (nnz + 3) / 4;
        scatter_kernel<<<(tgroups + 255) / 256, 256>>>(adj_src, adj_dst, adj_val, nnz);
    }

    // --- GEMM1 (TF32 + cp.async, fp16 H) ---
    cudaFuncSetAttribute(gemm1_tf32_v4,
                         cudaFuncAttributeMaxDynamicSharedMemorySize, GEMM1_SMEM);
    gemm1_tf32_v4<<<(n + 127) / 128, 256, GEMM1_SMEM>>>(x, W1, n);

    // --- SpMM1 (CSR, d=64): warp per row ---
    {
        long long total = (long long)n * 32;
        int blocks = (int)((total + 255) / 256);
        spmm64_csr_kernel<<<blocks, 256>>>(n);
    }
    // --- GEMM2 (fused relu + b1, fp16 Z1) ---
    gemm2_kernel<<<(n + 63) / 64, 256>>>(b1, W2, n);
    // --- SpMM2 (CSR, d=32): warp per row ---
    {
        long long total = (long long)n * 32;
        int blocks = (int)((total + 255) / 256);
        spmm32_csr_kernel<<<blocks, 256>>>(n);
    }
    // --- S2 -> fp16 with +b2 folded ---
    {
        int n4 = n * 8;
        s2half_kernel<<<(n4 + 255) / 256, 256>>>(b2, n4);
    }
    // --- Decoder: 1 warp per 32 edges ---
    {
        long long warps = ((long long)ne + 31) / 32;
        long long total = warps * 32;
        int blocks = (int)((total + 255) / 256);
        decoder_kernel<<<blocks, 256>>>(edge_idx, out, ne);
    }
}

// round 13
// speedup vs baseline: 1.5096x; 1.5096x over previous
#include <cuda_runtime.h>
#include <cuda_fp16.h>
#include <stdint.h>

#define D_IN   256
#define D_HID  64
#define D_EMB  32
#define MAX_NODES 100000

// Scratch (static __device__ — no allocation allowed)
__device__ __half g_Hh [MAX_NODES * D_HID];  // x @ W1            (fp16)
__device__ float  g_S1 [MAX_NODES * D_HID];  // A @ H             (fp32)
__device__ __half g_Z1h[MAX_NODES * D_EMB];  // relu(S1+b1) @ W2  (fp16)
__device__ float  g_S2 [MAX_NODES * D_EMB];  // A @ Z1            (fp32)
__device__ __half g_S2h[MAX_NODES * D_EMB];  // fp16 (S2+b2) for decoder

// ---------------------------------------------------------------------------
// TF32 helpers
// ---------------------------------------------------------------------------
__device__ __forceinline__ unsigned f2tf32(float f) {
    unsigned r;
    asm("cvt.rna.tf32.f32 %0, %1;" : "=r"(r) : "f"(f));
    return r;
}
__device__ __forceinline__ unsigned bits2tf32(unsigned b) {
    unsigned r;
    asm("cvt.rna.tf32.f32 %0, %1;" : "=r"(r) : "r"(b));
    return r;
}

__device__ __forceinline__ void mma_tf32(
    float& d0, float& d1, float& d2, float& d3,
    unsigned a0, unsigned a1, unsigned a2, unsigned a3,
    unsigned b0, unsigned b1)
{
    asm volatile(
        "mma.sync.aligned.m16n8k8.row.col.f32.tf32.tf32.f32 "
        "{%0,%1,%2,%3}, {%4,%5,%6,%7}, {%8,%9}, {%0,%1,%2,%3};"
        : "+f"(d0), "+f"(d1), "+f"(d2), "+f"(d3)
        : "r"(a0), "r"(a1), "r"(a2), "r"(a3), "r"(b0), "r"(b1));
}

__device__ __forceinline__ void cp_async16(unsigned smem_addr, const void* gptr) {
    asm volatile("cp.async.cg.shared.global [%0], [%1], 16;"
                 :: "r"(smem_addr), "l"(gptr));
}

// ---------------------------------------------------------------------------
// GEMM1 (TF32 + cp.async double buffer + fused zeroing), fp16 output
// ---------------------------------------------------------------------------
#define W_STRIDE 72
#define X_STRIDE 36
#define W_WORDS  (256 * W_STRIDE)
#define X_WORDS  (128 * X_STRIDE)
#define GEMM1_SMEM ((W_WORDS + 2 * X_WORDS) * 4)

__global__ __launch_bounds__(256) void gemm1_tf32_v4(
    const float* __restrict__ x, const float* __restrict__ W1, int n)
{
    extern __shared__ unsigned smem[];
    unsigned* Wsh = smem;                       // [256][72]
    float*    xsf = (float*)(smem + W_WORDS);   // [2][128][36]

    int tid  = threadIdx.x;
    int warp = tid >> 5;
    int lane = tid & 31;
    int row_base = blockIdx.x * 128;
    int wm   = warp * 16;
    int qrow = lane >> 2;
    int qcol = lane & 3;

    unsigned xs_base;
    asm("{ .reg .u64 t; cvta.to.shared.u64 t, %1; cvt.u32.u64 %0, t; }"
        : "=r"(xs_base) : "l"(xsf));

    #pragma unroll
    for (int l = 0; l < 4; l++) {
        int flat = tid + l * 256;
        int r    = flat >> 3;
        int c4   = flat & 7;
        int grow = row_base + r; if (grow >= n) grow = n - 1;
        cp_async16(xs_base + (unsigned)(r * X_STRIDE + c4 * 4) * 4,
                   x + (size_t)grow * D_IN + c4 * 4);
    }
    asm volatile("cp.async.commit_group;");

    #pragma unroll
    for (int l = 0; l < 16; l++) {
        int flat = tid + l * 256;
        int k  = flat >> 4;
        int cc = (flat & 15) * 4;
        float4 w = __ldg((const float4*)(W1 + (size_t)k * 64 + cc));
        Wsh[k * W_STRIDE + cc + 0] = f2tf32(w.x);
        Wsh[k * W_STRIDE + cc + 1] = f2tf32(w.y);
        Wsh[k * W_STRIDE + cc + 2] = f2tf32(w.z);
        Wsh[k * W_STRIDE + cc + 3] = f2tf32(w.w);
    }

    // fused zeroing of S1 / S2 (scatter targets)
    {
        int gtid = blockIdx.x * 256 + tid;
        int nthr = gridDim.x * 256;
        float4 z = make_float4(0.f, 0.f, 0.f, 0.f);
        for (int i = gtid; i < n * 16; i += nthr) ((float4*)g_S1)[i] = z;
        for (int i = gtid; i < n * 8;  i += nthr) ((float4*)g_S2)[i] = z;
    }

    float c[8][4];
    #pragma unroll
    for (int nt = 0; nt < 8; nt++)
        #pragma unroll
        for (int i = 0; i < 4; i++) c[nt][i] = 0.f;

    #pragma unroll
    for (int kc = 0; kc < 8; kc++) {
        if (kc + 1 < 8) {
            int buf = (kc + 1) & 1;
            #pragma unroll
            for (int l = 0; l < 4; l++) {
                int flat = tid + l * 256;
                int r    = flat >> 3;
                int c4   = flat & 7;
                int grow = row_base + r; if (grow >= n) grow = n - 1;
                cp_async16(xs_base + (unsigned)(buf * X_WORDS + r * X_STRIDE + c4 * 4) * 4,
                           x + (size_t)grow * D_IN + (kc + 1) * 32 + c4 * 4);
            }
            asm volatile("cp.async.commit_group;");
            asm volatile("cp.async.wait_group 1;");
        } else {
            asm volatile("cp.async.wait_group 0;");
        }
        __syncthreads();

        const unsigned* xb = (const unsigned*)(xsf + (kc & 1) * X_WORDS);
        #pragma unroll
        for (int k8 = 0; k8 < 4; k8++) {
            int ar = wm + qrow;
            int ac = k8 * 8 + qcol;
            unsigned a0 = bits2tf32(xb[(ar    ) * X_STRIDE + ac    ]);
            unsigned a1 = bits2tf32(xb[(ar + 8) * X_STRIDE + ac    ]);
            unsigned a2 = bits2tf32(xb[(ar    ) * X_STRIDE + ac + 4]);
            unsigned a3 = bits2tf32(xb[(ar + 8) * X_STRIDE + ac + 4]);
            int kg = kc * 32 + k8 * 8 + qcol;
            #pragma unroll
            for (int nt = 0; nt < 8; nt++) {
                unsigned b0 = Wsh[(kg    ) * W_STRIDE + nt * 8 + qrow];
                unsigned b1 = Wsh[(kg + 4) * W_STRIDE + nt * 8 + qrow];
                mma_tf32(c[nt][0], c[nt][1], c[nt][2], c[nt][3],
                         a0, a1, a2, a3, b0, b1);
            }
        }
        __syncthreads();
    }

    int r0 = row_base + wm + qrow;
    int cb = qcol * 2;
    #pragma unroll
    for (int nt = 0; nt < 8; nt++) {
        if (r0 < n)
            *(__half2*)(g_Hh + (size_t)r0 * D_HID + nt*8 + cb) =
                __floats2half2_rn(c[nt][0], c[nt][1]);
        if (r0 + 8 < n)
            *(__half2*)(g_Hh + (size_t)(r0 + 8) * D_HID + nt*8 + cb) =
                __floats2half2_rn(c[nt][2], c[nt][3]);
    }
}

// ---------------------------------------------------------------------------
// red.v4 helper
// ---------------------------------------------------------------------------
__device__ __forceinline__ void red_add_v4(float* p, float4 v) {
    asm volatile("red.global.add.v4.f32 [%0], {%1,%2,%3,%4};"
                 :: "l"(p), "f"(v.x), "f"(v.y), "f"(v.z), "f"(v.w)
                 : "memory");
}

// ---------------------------------------------------------------------------
// SpMM d=64: warp owns 32 edges; coalesced streaming index loads + shfl.
// ---------------------------------------------------------------------------
__global__ __launch_bounds__(256) void spmm64_kernel(
    const int* __restrict__ src, const int* __restrict__ dst,
    const float* __restrict__ val, int nnz)
{
    int lane = threadIdx.x & 31;
    long long wid = (long long)((blockIdx.x * blockDim.x + threadIdx.x) >> 5);
    long long wbase = wid * 32;
    if (wbase >= nnz) return;

    long long e = wbase + lane;
    bool ok = (e < nnz);
    long long ec = ok ? e : (nnz - 1);
    int   s = __ldcs(src + ec);
    int   d = __ldcs(dst + ec);
    float v = ok ? __ldcs(val + ec) : 0.f;

    int g = lane >> 4;          // group 0/1
    int c = lane & 15;          // channel quad

    #pragma unroll
    for (int j = 0; j < 16; j++) {
        int sl = g * 16 + j;
        int   sj = __shfl_sync(0xFFFFFFFFu, s, sl);
        int   dj = __shfl_sync(0xFFFFFFFFu, d, sl);
        float vj = __shfl_sync(0xFFFFFFFFu, v, sl);
        uint2 raw = __ldg((const uint2*)(g_Hh + (size_t)sj * D_HID) + c);
        float2 f0 = __half22float2(*(__half2*)&raw.x);
        float2 f1 = __half22float2(*(__half2*)&raw.y);
        red_add_v4(g_S1 + (size_t)dj * D_HID + c * 4,
                   make_float4(vj*f0.x, vj*f0.y, vj*f1.x, vj*f1.y));
    }
}

// ---------------------------------------------------------------------------
// GEMM2 (TF32 MMA): Z1 = relu(S1 + b1) @ W2   [n,64] @ [64,32], fp16 out.
// 256 threads = 8 warps, block 128 rows (warp tile 16x32), single K pass.
// ---------------------------------------------------------------------------
#define Z_STRIDE 68    // S1 tile row stride (words): 68 % 32 == 4 -> conflict-free frags
#define V_STRIDE 40    // W2 row stride (words): 8*qcol+qrow all-distinct banks

__global__ __launch_bounds__(256) void gemm2_mma_kernel(
    const float* __restrict__ b1, const float* __restrict__ W2, int n)
{
    __shared__ float    zs[128 * Z_STRIDE];    // 34816 B
    __shared__ unsigned ws[64 * V_STRIDE];     // 10240 B (tf32 W2)
    __shared__ float    b1s[64];

    int tid  = threadIdx.x;
    int warp = tid >> 5;
    int lane = tid & 31;
    int row_base = blockIdx.x * 128;
    int wm   = warp * 16;
    int qrow = lane >> 2;
    int qcol = lane & 3;

    unsigned zs_base;
    asm("{ .reg .u64 t; cvta.to.shared.u64 t, %1; cvt.u32.u64 %0, t; }"
        : "=r"(zs_base) : "l"(zs));

    // stage S1 tile: 128 rows x 64 f32 = 2048 float4 (cp.async)
    #pragma unroll
    for (int l = 0; l < 8; l++) {
        int flat = tid + l * 256;
        int r  = flat >> 4;              // 16 float4 per row
        int c4 = flat & 15;
        int grow = row_base + r; if (grow >= n) grow = n - 1;
        cp_async16(zs_base + (unsigned)(r * Z_STRIDE + c4 * 4) * 4,
                   g_S1 + (size_t)grow * D_HID + c4 * 4);
    }
    asm volatile("cp.async.commit_group;");

    // stage W2 (64x32) as tf32, stride V_STRIDE
    #pragma unroll
    for (int l = 0; l < 2; l++) {
        int flat = tid + l * 256;        // float4 index over 512
        int k  = flat >> 3;              // 8 float4 per k-row
        int cc = (flat & 7) * 4;
        float4 w = __ldg((const float4*)(W2 + (size_t)k * 32 + cc));
        ws[k * V_STRIDE + cc + 0] = f2tf32(w.x);
        ws[k * V_STRIDE + cc + 1] = f2tf32(w.y);
        ws[k * V_STRIDE + cc + 2] = f2tf32(w.z);
        ws[k * V_STRIDE + cc + 3] = f2tf32(w.w);
    }
    if (tid < 64) b1s[tid] = __ldg(b1 + tid);

    asm volatile("cp.async.wait_group 0;");
    __syncthreads();

    float c[4][4];
    #pragma unroll
    for (int nt = 0; nt < 4; nt++)
        #pragma unroll
        for (int i = 0; i < 4; i++) c[nt][i] = 0.f;

    int ar = wm + qrow;
    #pragma unroll
    for (int k8 = 0; k8 < 8; k8++) {
        int k0 = k8 * 8 + qcol;
        float bz0 = b1s[k0];
        float bz1 = b1s[k0 + 4];
        unsigned a0 = f2tf32(fmaxf(zs[(ar    ) * Z_STRIDE + k0    ] + bz0, 0.f));
        unsigned a1 = f2tf32(fmaxf(zs[(ar + 8) * Z_STRIDE + k0    ] + bz0, 0.f));
        unsigned a2 = f2tf32(fmaxf(zs[(ar    ) * Z_STRIDE + k0 + 4] + bz1, 0.f));
        unsigned a3 = f2tf32(fmaxf(zs[(ar + 8) * Z_STRIDE + k0 + 4] + bz1, 0.f));
        #pragma unroll
        for (int nt = 0; nt < 4; nt++) {
            unsigned b0 = ws[(k0    ) * V_STRIDE + nt * 8 + qrow];
            unsigned b1v= ws[(k0 + 4) * V_STRIDE + nt * 8 + qrow];
            mma_tf32(c[nt][0], c[nt][1], c[nt][2], c[nt][3],
                     a0, a1, a2, a3, b0, b1v);
        }
    }

    int r0 = row_base + wm + qrow;
    int cb = qcol * 2;
    #pragma unroll
    for (int nt = 0; nt < 4; nt++) {
        if (r0 < n)
            *(__half2*)(g_Z1h + (size_t)r0 * D_EMB + nt*8 + cb) =
                __floats2half2_rn(c[nt][0], c[nt][1]);
        if (r0 + 8 < n)
            *(__half2*)(g_Z1h + (size_t)(r0 + 8) * D_EMB + nt*8 + cb) =
                __floats2half2_rn(c[nt][2], c[nt][3]);
    }
}

// ---------------------------------------------------------------------------
// SpMM d=32: warp owns 32 edges; coalesced streaming index loads + shfl.
// ---------------------------------------------------------------------------
__global__ __launch_bounds__(256) void spmm32_kernel(
    const int* __restrict__ src, const int* __restrict__ dst,
    const float* __restrict__ val, int nnz)
{
    int lane = threadIdx.x & 31;
    long long wid = (long long)((blockIdx.x * blockDim.x + threadIdx.x) >> 5);
    long long wbase = wid * 32;
    if (wbase >= nnz) return;

    long long e = wbase + lane;
    bool ok = (e < nnz);
    long long ec = ok ? e : (nnz - 1);
    int   s = __ldcs(src + ec);
    int   d = __ldcs(dst + ec);
    float v = ok ? __ldcs(val + ec) : 0.f;

    int g = lane >> 3;          // group 0..3
    int c = lane & 7;

    #pragma unroll
    for (int j = 0; j < 8; j++) {
        int sl = g * 8 + j;
        int   sj = __shfl_sync(0xFFFFFFFFu, s, sl);
        int   dj = __shfl_sync(0xFFFFFFFFu, d, sl);
        float vj = __shfl_sync(0xFFFFFFFFu, v, sl);
        uint2 raw = __ldg((const uint2*)(g_Z1h + (size_t)sj * D_EMB) + c);
        float2 f0 = __half22float2(*(__half2*)&raw.x);
        float2 f1 = __half22float2(*(__half2*)&raw.y);
        red_add_v4(g_S2 + (size_t)dj * D_EMB + c * 4,
                   make_float4(vj*f0.x, vj*f0.y, vj*f1.x, vj*f1.y));
    }
}

// ---------------------------------------------------------------------------
// S2 fp32 -> fp16 with fused +b2.
// ---------------------------------------------------------------------------
__global__ __launch_bounds__(256) void s2half_kernel(
    const float* __restrict__ b2, int n4)
{
    int i = blockIdx.x * blockDim.x + threadIdx.x;
    if (i >= n4) return;
    float4 bb = __ldg((const float4*)b2 + (i & 7));
    float4 v = ((const float4*)g_S2)[i];
    ((__half2*)g_S2h)[i*2    ] = __floats2half2_rn(v.x + bb.x, v.y + bb.y);
    ((__half2*)g_S2h)[i*2 + 1] = __floats2half2_rn(v.z + bb.z, v.w + bb.w);
}

// ---------------------------------------------------------------------------
// Decoder: warp owns 32 edges; coalesced index loads + shfl distribution.
// ---------------------------------------------------------------------------
__global__ __launch_bounds__(256) void decoder_kernel(
    const int* __restrict__ edge_index, float* __restrict__ out, int ne)
{
    int lane = threadIdx.x & 31;
    long long wid = (long long)((blockIdx.x * blockDim.x + threadIdx.x) >> 5);
    long long wbase = wid * 32;
    if (wbase >= ne) return;

    long long e = wbase + lane;
    bool ok = (e < ne);
    long long ec = ok ? e : (ne - 1);
    int s = __ldcs(edge_index + ec);
    int d = __ldcs(edge_index + ne + ec);

    int g = lane >> 3;
    int c = lane & 7;

    float p[8];
    #pragma unroll
    for (int j = 0; j < 8; j++) {
        int sl = g * 8 + j;
        int sj = __shfl_sync(0xFFFFFFFFu, s, sl);
        int dj = __shfl_sync(0xFFFFFFFFu, d, sl);
        uint2 ra = __ldg((const uint2*)(g_S2h + (size_t)sj * D_EMB) + c);
        uint2 rb = __ldg((const uint2*)(g_S2h + (size_t)dj * D_EMB) + c);
        float2 al = __half22float2(*(__half2*)&ra.x);
        float2 ah = __half22float2(*(__half2*)&ra.y);
        float2 bl = __half22float2(*(__half2*)&rb.x);
        float2 bh = __half22float2(*(__half2*)&rb.y);
        p[j] = al.x*bl.x + al.y*bl.y + ah.x*bh.x + ah.y*bh.y;
    }

    #pragma unroll
    for (int m = 1; m < 8; m <<= 1) {
        #pragma unroll
        for (int j = 0; j < 8; j++)
            p[j] += __shfl_xor_sync(0xFFFFFFFFu, p[j], m);
    }

    long long eo = wbase + g * 8 + c;
    if (eo < ne) out[eo] = p[c];
}

// ---------------------------------------------------------------------------
extern "C" void kernel_launch(void* const* d_in, const int* in_sizes, int n_in,
                              void* d_out, int out_size)
{
    const float* x         = (const float*)d_in[0];
    const int*   adj_src   = (const int*)  d_in[1];
    const int*   adj_dst   = (const int*)  d_in[2];
    const float* adj_val   = (const float*)d_in[3];
    const int*   edge_idx  = (const int*)  d_in[4];
    const float* W1        = (const float*)d_in[5];
    const float* b1        = (const float*)d_in[6];
    const float* W2        = (const float*)d_in[7];
    const float* b2        = (const float*)d_in[8];
    float*       out       = (float*)d_out;

    int n   = in_sizes[0] / D_IN;
    int nnz = in_sizes[3];
    int ne  = in_sizes[4] / 2;
    (void)n_in; (void)out_size;

    // GEMM1 (TF32 + cp.async, fused S1/S2 zeroing, fp16 H)
    cudaFuncSetAttribute(gemm1_tf32_v4,
                         cudaFuncAttributeMaxDynamicSharedMemorySize, GEMM1_SMEM);
    gemm1_tf32_v4<<<(n + 127) / 128, 256, GEMM1_SMEM>>>(x, W1, n);

    // SpMM1 (d=64): 1 warp per 32 edges
    {
        long long warps = ((long long)nnz + 31) / 32;
        long long total = warps * 32;
        int blocks = (int)((total + 255) / 256);
        spmm64_kernel<<<blocks, 256>>>(adj_src, adj_dst, adj_val, nnz);
    }
    // GEMM2 (TF32 MMA, fused relu + b1, fp16 Z1)
    gemm2_mma_kernel<<<(n + 127) / 128, 256>>>(b1, W2, n);
    // SpMM2 (d=32): 1 warp per 32 edges
    {
        long long warps = ((long long)nnz + 31) / 32;
        long long total = warps * 32;
        int blocks = (int)((total + 255) / 256);
        spmm32_kernel<<<blocks, 256>>>(adj_src, adj_dst, adj_val, nnz);
    }
    // S2 -> fp16 with +b2 folded
    {
        int n4 = n * 8;
        s2half_kernel<<<(n4 + 255) / 256, 256>>>(b2, n4);
    }
    // Decoder: 1 warp per 32 edges
    {
        long long warps = ((long long)ne + 31) / 32;
        long long total = warps * 32;
        int blocks = (int)((total + 255) / 256);
        decoder_kernel<<<blocks, 256>>>(edge_idx, out, ne);
    }
}